// round 1
// baseline (speedup 1.0000x reference)
#include <cuda_runtime.h>
#include <cuda_bf16.h>
#include <math.h>

// Problem constants
#define NSEG   4096
#define NVOT   1048576
#define NCAND  32
#define EMB    128

#define TM      128      // voters per CTA tile
#define THREADS 256
#define SX_STRIDE 36     // padded stride for x tile (avoid bank conflicts)
#define SH_STRIDE 132    // padded stride for h tiles

// Scratch for segment sums (allocation-free rule: __device__ global array)
__device__ float g_agg[NSEG * EMB];

// smem layout (floats): sW[128*128] | sA[128*132] | sB[128*132] | sX[128*36]
#define SW_ELEMS (128*128)
#define SH_ELEMS (128*SH_STRIDE)
#define SX_ELEMS (128*SX_STRIDE)
#define SMEM_FLOATS (SW_ELEMS + 2*SH_ELEMS + SX_ELEMS)
#define SMEM_BYTES (SMEM_FLOATS * 4)

__global__ void zero_agg_kernel() {
    int i = blockIdx.x * blockDim.x + threadIdx.x;
    if (i < NSEG * EMB) g_agg[i] = 0.0f;
}

// Register-tiled 128x128(xK) MMA over shared tiles.
// A: [128 rows x K], row stride ASTRIDE. B: [K x 128], row stride 128.
template <int K, int ASTRIDE>
__device__ __forceinline__ void tile_mma(const float* __restrict__ A,
                                         const float* __restrict__ B,
                                         float acc[8][8], int r0, int c0) {
#pragma unroll 4
    for (int k = 0; k < K; ++k) {
        float a[8];
#pragma unroll
        for (int i = 0; i < 8; ++i) a[i] = A[(r0 + i) * ASTRIDE + k];
        float4 b0 = *reinterpret_cast<const float4*>(B + k * 128 + c0);
        float4 b1 = *reinterpret_cast<const float4*>(B + k * 128 + c0 + 4);
        float b[8] = {b0.x, b0.y, b0.z, b0.w, b1.x, b1.y, b1.z, b1.w};
#pragma unroll
        for (int i = 0; i < 8; ++i)
#pragma unroll
            for (int j = 0; j < 8; ++j)
                acc[i][j] += a[i] * b[j];
    }
}

__global__ __launch_bounds__(THREADS, 1)
void local_mlp_kernel(const float* __restrict__ x, const int* __restrict__ index,
                      const float* __restrict__ lW1, const float* __restrict__ lb1,
                      const float* __restrict__ lW2, const float* __restrict__ lb2,
                      const float* __restrict__ lW3, const float* __restrict__ lb3) {
    extern __shared__ float sm[];
    float* sW = sm;                       // current layer weight (row-major [K,128])
    float* sA = sW + SW_ELEMS;            // h buffer A (stride 132)
    float* sB = sA + SH_ELEMS;            // h buffer B (stride 132)
    float* sX = sB + SH_ELEMS;            // x tile (stride 36)
    __shared__ float sBias[EMB];
    __shared__ int   sIdx[TM];

    const int tid = threadIdx.x;
    const long long v0 = (long long)blockIdx.x * TM;

    // ---- stage x tile + W1 + b1 + indices ----
    {
        const float4* xg = reinterpret_cast<const float4*>(x + v0 * NCAND);
        for (int t = tid; t < TM * NCAND / 4; t += THREADS) {
            float4 v = xg[t];
            int row = t >> 3;          // 8 float4 per 32-wide row
            int c4  = (t & 7) * 4;
            float* dst = sX + row * SX_STRIDE + c4;
            dst[0] = v.x; dst[1] = v.y; dst[2] = v.z; dst[3] = v.w;
        }
        const float4* wg = reinterpret_cast<const float4*>(lW1);
        float4* ws = reinterpret_cast<float4*>(sW);
        for (int t = tid; t < NCAND * EMB / 4; t += THREADS) ws[t] = wg[t];
        if (tid < EMB) sBias[tid] = lb1[tid];
        if (tid < TM)  sIdx[tid]  = index[v0 + tid];
    }
    __syncthreads();

    const int ty = tid >> 4, tx = tid & 15;
    const int r0 = ty * 8, c0 = tx * 8;
    float acc[8][8];

    // ---- layer 1: relu(x @ W1 + b1) -> sA ----
#pragma unroll
    for (int i = 0; i < 8; ++i)
#pragma unroll
        for (int j = 0; j < 8; ++j) acc[i][j] = 0.0f;
    tile_mma<NCAND, SX_STRIDE>(sX, sW, acc, r0, c0);
#pragma unroll
    for (int i = 0; i < 8; ++i)
#pragma unroll
        for (int j = 0; j < 8; ++j)
            sA[(r0 + i) * SH_STRIDE + c0 + j] = fmaxf(acc[i][j] + sBias[c0 + j], 0.0f);
    __syncthreads();

    // stage W2 + b2
    {
        const float4* wg = reinterpret_cast<const float4*>(lW2);
        float4* ws = reinterpret_cast<float4*>(sW);
        for (int t = tid; t < EMB * EMB / 4; t += THREADS) ws[t] = wg[t];
        if (tid < EMB) sBias[tid] = lb2[tid];
    }
    __syncthreads();

    // ---- layer 2: relu(h1 @ W2 + b2) -> sB ----
#pragma unroll
    for (int i = 0; i < 8; ++i)
#pragma unroll
        for (int j = 0; j < 8; ++j) acc[i][j] = 0.0f;
    tile_mma<EMB, SH_STRIDE>(sA, sW, acc, r0, c0);
#pragma unroll
    for (int i = 0; i < 8; ++i)
#pragma unroll
        for (int j = 0; j < 8; ++j)
            sB[(r0 + i) * SH_STRIDE + c0 + j] = fmaxf(acc[i][j] + sBias[c0 + j], 0.0f);
    __syncthreads();

    // stage W3 + b3
    {
        const float4* wg = reinterpret_cast<const float4*>(lW3);
        float4* ws = reinterpret_cast<float4*>(sW);
        for (int t = tid; t < EMB * EMB / 4; t += THREADS) ws[t] = wg[t];
        if (tid < EMB) sBias[tid] = lb3[tid];
    }
    __syncthreads();

    // ---- layer 3: h2 @ W3 + b3 (no relu) -> sA (safe: sA no longer read) ----
#pragma unroll
    for (int i = 0; i < 8; ++i)
#pragma unroll
        for (int j = 0; j < 8; ++j) acc[i][j] = 0.0f;
    tile_mma<EMB, SH_STRIDE>(sB, sW, acc, r0, c0);
#pragma unroll
    for (int i = 0; i < 8; ++i)
#pragma unroll
        for (int j = 0; j < 8; ++j)
            sA[(r0 + i) * SH_STRIDE + c0 + j] = acc[i][j] + sBias[c0 + j];
    __syncthreads();

    // ---- in-CTA segment reduction (index is globally sorted) ----
    if (tid < EMB) {
        const int col = tid;
        int cur = sIdx[0];
        float s = 0.0f;
#pragma unroll 4
        for (int r = 0; r < TM; ++r) {
            int idx = sIdx[r];
            if (idx != cur) {
                atomicAdd(&g_agg[(long long)cur * EMB + col], s);
                s = 0.0f;
                cur = idx;
            }
            s += sA[r * SH_STRIDE + col];
        }
        atomicAdd(&g_agg[(long long)cur * EMB + col], s);
    }
}

__global__ __launch_bounds__(128)
void global_mlp_kernel(const float* __restrict__ gW1, const float* __restrict__ gb1,
                       const float* __restrict__ gW2, const float* __restrict__ gb2,
                       const float* __restrict__ gW3, const float* __restrict__ gb3,
                       float* __restrict__ out) {
    __shared__ float sIn[EMB];
    __shared__ float sH[EMB];
    const int tid = threadIdx.x;
    const int seg = blockIdx.x;

    sIn[tid] = g_agg[seg * EMB + tid];
    __syncthreads();

    // layer g1
    float acc = gb1[tid];
#pragma unroll 8
    for (int k = 0; k < EMB; ++k) acc += sIn[k] * gW1[k * EMB + tid];
    sH[tid] = fmaxf(acc, 0.0f);
    __syncthreads();

    // layer g2 (write back into sIn; all sIn reads finished before this barrier)
    acc = gb2[tid];
#pragma unroll 8
    for (int k = 0; k < EMB; ++k) acc += sH[k] * gW2[k * EMB + tid];
    __syncthreads();
    sIn[tid] = fmaxf(acc, 0.0f);
    __syncthreads();

    // scores + log_softmax (warp 0)
    if (tid < NCAND) {
        float sc = gb3[tid];
#pragma unroll 8
        for (int k = 0; k < EMB; ++k) sc += sIn[k] * gW3[k * NCAND + tid];
        float m = sc;
#pragma unroll
        for (int o = 16; o > 0; o >>= 1) m = fmaxf(m, __shfl_xor_sync(0xffffffffu, m, o));
        float e = expf(sc - m);
        float ssum = e;
#pragma unroll
        for (int o = 16; o > 0; o >>= 1) ssum += __shfl_xor_sync(0xffffffffu, ssum, o);
        out[seg * NCAND + tid] = sc - m - logf(ssum);
    }
}

extern "C" void kernel_launch(void* const* d_in, const int* in_sizes, int n_in,
                              void* d_out, int out_size) {
    const float* x     = (const float*)d_in[0];
    const int*   index = (const int*)d_in[1];
    const float* lW1 = (const float*)d_in[2];
    const float* lb1 = (const float*)d_in[3];
    const float* lW2 = (const float*)d_in[4];
    const float* lb2 = (const float*)d_in[5];
    const float* lW3 = (const float*)d_in[6];
    const float* lb3 = (const float*)d_in[7];
    const float* gW1 = (const float*)d_in[8];
    const float* gb1 = (const float*)d_in[9];
    const float* gW2 = (const float*)d_in[10];
    const float* gb2 = (const float*)d_in[11];
    const float* gW3 = (const float*)d_in[12];
    const float* gb3 = (const float*)d_in[13];
    float* out = (float*)d_out;

    cudaFuncSetAttribute(local_mlp_kernel,
                         cudaFuncAttributeMaxDynamicSharedMemorySize, SMEM_BYTES);

    zero_agg_kernel<<<(NSEG * EMB + 255) / 256, 256>>>();
    local_mlp_kernel<<<NVOT / TM, THREADS, SMEM_BYTES>>>(x, index,
                                                         lW1, lb1, lW2, lb2, lW3, lb3);
    global_mlp_kernel<<<NSEG, 128>>>(gW1, gb1, gW2, gb2, gW3, gb3, out);
}